// round 1
// baseline (speedup 1.0000x reference)
#include <cuda_runtime.h>

#define T_LEN 4096
#define B_SZ  512
#define NIN   42
#define NH    9
#define G4    36            // 4*NH
#define ROWS  (T_LEN * B_SZ) // 2097152
#define KP    44             // padded K for kernel1 (multiple of 4)
#define RT    128            // rows per block in kernel1
#define STRIDE (B_SZ * NH)   // 4608

// Scratch: precomputed gates (i,f,g,o) per (row, j), biases folded in. ~302 MB.
__device__ float4 g_xpre[(size_t)ROWS * NH];

// ---------------------------------------------------------------------------
// Kernel 1: x_pre[row][j][{i,f,g,o}] = x[row] . W_ih[gate*9+j] + b_ih + b_hh
// Register-tiled fp32 GEMM: 9 warps/block (warp = j), lane handles 4 rows,
// thread computes 4 gates x 4 rows. W chunks via broadcast LDS.128.
// ---------------------------------------------------------------------------
__global__ __launch_bounds__(288) void xproj_kernel(
    const float* __restrict__ x, const float* __restrict__ Wih,
    const float* __restrict__ bih, const float* __restrict__ bhh)
{
    __shared__ float xs[RT * KP];
    __shared__ float ws[G4 * KP];
    const int tid  = threadIdx.x;
    const int row0 = blockIdx.x * RT;

    // Load W_ih into smem, reindexed so gate rows for unit j are adjacent:
    // ws[(j*4+g)*KP + k] = W_ih[(g*9+j)*42 + k]
    for (int i = tid; i < G4 * NIN; i += 288) {
        int r = i / NIN, k = i - r * NIN;
        int g = r / NH,  j = r - g * NH;
        ws[(j * 4 + g) * KP + k] = Wih[i];
    }
    for (int i = tid; i < G4 * (KP - NIN); i += 288) {
        int r = i / (KP - NIN);
        ws[r * KP + NIN + (i - r * (KP - NIN))] = 0.f;
    }
    // Load x tile (contiguous global span), pad cols 42..43 with zero.
    const float* xg = x + (size_t)row0 * NIN;
    for (int i = tid; i < RT * NIN; i += 288) {
        int r = i / NIN;
        xs[r * KP + (i - r * NIN)] = xg[i];
    }
    for (int i = tid; i < RT * (KP - NIN); i += 288) {
        int r = i >> 1;
        xs[r * KP + NIN + (i & 1)] = 0.f;
    }
    __syncthreads();

    const int j    = tid >> 5;   // warp index = hidden unit j (0..8)
    const int lane = tid & 31;

    float acc[4][4];
    #pragma unroll
    for (int r = 0; r < 4; r++)
        #pragma unroll
        for (int g = 0; g < 4; g++) acc[r][g] = 0.f;

    const float4* wv = (const float4*)ws + j * 4 * (KP / 4);
    const float4* xv = (const float4*)xs;

    #pragma unroll
    for (int cch = 0; cch < KP / 4; cch++) {
        float4 w0 = wv[0 * (KP / 4) + cch];
        float4 w1 = wv[1 * (KP / 4) + cch];
        float4 w2 = wv[2 * (KP / 4) + cch];
        float4 w3 = wv[3 * (KP / 4) + cch];
        #pragma unroll
        for (int r = 0; r < 4; r++) {
            float4 xr = xv[(lane + 32 * r) * (KP / 4) + cch];
            acc[r][0] = fmaf(w0.x, xr.x, acc[r][0]);
            acc[r][0] = fmaf(w0.y, xr.y, acc[r][0]);
            acc[r][0] = fmaf(w0.z, xr.z, acc[r][0]);
            acc[r][0] = fmaf(w0.w, xr.w, acc[r][0]);
            acc[r][1] = fmaf(w1.x, xr.x, acc[r][1]);
            acc[r][1] = fmaf(w1.y, xr.y, acc[r][1]);
            acc[r][1] = fmaf(w1.z, xr.z, acc[r][1]);
            acc[r][1] = fmaf(w1.w, xr.w, acc[r][1]);
            acc[r][2] = fmaf(w2.x, xr.x, acc[r][2]);
            acc[r][2] = fmaf(w2.y, xr.y, acc[r][2]);
            acc[r][2] = fmaf(w2.z, xr.z, acc[r][2]);
            acc[r][2] = fmaf(w2.w, xr.w, acc[r][2]);
            acc[r][3] = fmaf(w3.x, xr.x, acc[r][3]);
            acc[r][3] = fmaf(w3.y, xr.y, acc[r][3]);
            acc[r][3] = fmaf(w3.z, xr.z, acc[r][3]);
            acc[r][3] = fmaf(w3.w, xr.w, acc[r][3]);
        }
    }

    float bsum[4];
    #pragma unroll
    for (int g = 0; g < 4; g++) bsum[g] = bih[g * NH + j] + bhh[g * NH + j];

    #pragma unroll
    for (int r = 0; r < 4; r++) {
        int row = row0 + lane + 32 * r;
        float4 o;
        o.x = acc[r][0] + bsum[0];
        o.y = acc[r][1] + bsum[1];
        o.z = acc[r][2] + bsum[2];
        o.w = acc[r][3] + bsum[3];
        g_xpre[(size_t)row * NH + j] = o;
    }
}

// ---------------------------------------------------------------------------
// Kernel 2: sequential recurrence. 1 warp/block, 3 batch elements per warp
// (lanes 0-8, 9-17, 18-26), lane j owns hidden unit j. W_hh in registers,
// h exchanged via __shfl_sync, x_pre prefetched 4 steps ahead.
// ---------------------------------------------------------------------------
__device__ __forceinline__ float sigf(float v) {
    return __fdividef(1.f, 1.f + __expf(-v));
}
__device__ __forceinline__ float tanhf_fast(float v) {
    return __fdividef(2.f, 1.f + __expf(-2.f * v)) - 1.f;
}

#define LSTM_STEP(XP, TT) do {                                                \
    float a0 = (XP).x, a1 = (XP).y, a2 = (XP).z, a3 = (XP).w;                 \
    float d0 = 0.f, d1 = 0.f, d2 = 0.f, d3 = 0.f;                             \
    _Pragma("unroll")                                                         \
    for (int k = 0; k < 9; k++) {                                             \
        float hk = __shfl_sync(0xFFFFFFFFu, h, base + k);                     \
        if (k < 5) {                                                          \
            a0 = fmaf(Wi[k], hk, a0); a1 = fmaf(Wf[k], hk, a1);               \
            a2 = fmaf(Wg[k], hk, a2); a3 = fmaf(Wo[k], hk, a3);               \
        } else {                                                              \
            d0 = fmaf(Wi[k], hk, d0); d1 = fmaf(Wf[k], hk, d1);               \
            d2 = fmaf(Wg[k], hk, d2); d3 = fmaf(Wo[k], hk, d3);               \
        }                                                                     \
    }                                                                         \
    float ig = sigf(a0 + d0);                                                 \
    float fg = sigf(a1 + d1);                                                 \
    float gg = tanhf_fast(a2 + d2);                                           \
    float og = sigf(a3 + d3);                                                 \
    c = fmaf(fg, c, ig * gg);                                                 \
    h = og * tanhf_fast(c);                                                   \
    if (valid) out[(TT) * STRIDE + base_idx] = h;                             \
} while (0)

__global__ __launch_bounds__(32) void lstm_rec_kernel(
    const float* __restrict__ h_in, const float* __restrict__ c_in,
    const float* __restrict__ Whh, float* __restrict__ out)
{
    const int lane  = threadIdx.x;
    const int group = (lane < 27) ? (lane / 9) : 2;  // element within warp
    const int u     = lane - group * 9;
    const int j     = (u < 9) ? u : 0;
    const int base  = group * 9;                     // shfl base lane
    const int b0    = blockIdx.x * 3 + group;
    const bool valid = (lane < 27) && (b0 < B_SZ);
    const int b     = (b0 < B_SZ) ? b0 : (B_SZ - 1);

    float Wi[NH], Wf[NH], Wg[NH], Wo[NH];
    #pragma unroll
    for (int k = 0; k < NH; k++) {
        Wi[k] = Whh[(0 * NH + j) * NH + k];
        Wf[k] = Whh[(1 * NH + j) * NH + k];
        Wg[k] = Whh[(2 * NH + j) * NH + k];
        Wo[k] = Whh[(3 * NH + j) * NH + k];
    }
    float h = h_in[b * NH + j];
    float c = c_in[b * NH + j];

    const int base_idx = b * NH + j;
    const float4* xp = g_xpre;  // index: t*STRIDE + base_idx

    float4 f0 = xp[0 * STRIDE + base_idx];
    float4 f1 = xp[1 * STRIDE + base_idx];
    float4 f2 = xp[2 * STRIDE + base_idx];
    float4 f3 = xp[3 * STRIDE + base_idx];

    int t = 0;
    for (; t < T_LEN - 4; t += 4) {
        // issue next 4 prefetches first so they are in flight during compute
        float4 n0 = xp[(t + 4) * STRIDE + base_idx];
        float4 n1 = xp[(t + 5) * STRIDE + base_idx];
        float4 n2 = xp[(t + 6) * STRIDE + base_idx];
        float4 n3 = xp[(t + 7) * STRIDE + base_idx];
        LSTM_STEP(f0, t + 0);
        LSTM_STEP(f1, t + 1);
        LSTM_STEP(f2, t + 2);
        LSTM_STEP(f3, t + 3);
        f0 = n0; f1 = n1; f2 = n2; f3 = n3;
    }
    // tail: t = 4092..4095
    LSTM_STEP(f0, t + 0);
    LSTM_STEP(f1, t + 1);
    LSTM_STEP(f2, t + 2);
    LSTM_STEP(f3, t + 3);

    if (valid) {
        out[(size_t)T_LEN * STRIDE + base_idx]          = h;  // hn
        out[(size_t)T_LEN * STRIDE + STRIDE + base_idx] = c;  // cn
    }
}

// ---------------------------------------------------------------------------
extern "C" void kernel_launch(void* const* d_in, const int* in_sizes, int n_in,
                              void* d_out, int out_size) {
    const float* x   = (const float*)d_in[0];
    const float* h   = (const float*)d_in[1];
    const float* c   = (const float*)d_in[2];
    const float* Wih = (const float*)d_in[3];
    const float* Whh = (const float*)d_in[4];
    const float* bih = (const float*)d_in[5];
    const float* bhh = (const float*)d_in[6];
    float* out = (float*)d_out;

    xproj_kernel<<<ROWS / RT, 288>>>(x, Wih, bih, bhh);
    lstm_rec_kernel<<<(B_SZ + 2) / 3, 32>>>(h, c, Whh, out);
}